// round 1
// baseline (speedup 1.0000x reference)
#include <cuda_runtime.h>

#define D 512
#define BN 1024          // B*N = 8*128
#define NPAIR 128        // m per (b,n)
#define L2DIM 256        // W2 output width

typedef unsigned long long ull;

// Scratch (allocation-free rule: __device__ globals)
__device__ float g_A[BN * D];   // h1 + pc + b1   (indexed by n-row)
__device__ float g_B[BN * D];   // h2 - pc        (indexed by m-row)

// ---------------- f32x2 packed-FMA helpers ----------------
__device__ __forceinline__ void ffma2(ull &acc, ull a, ull b) {
    asm("fma.rn.f32x2 %0, %1, %2, %0;" : "+l"(acc) : "l"(a), "l"(b));
}
__device__ __forceinline__ ull pack2(float x, float y) {
    ull r;
    asm("mov.b64 %0, {%1, %2};" : "=l"(r) : "f"(x), "f"(y));
    return r;
}
__device__ __forceinline__ float2 unpack2(ull v) {
    float2 r;
    asm("mov.b64 {%0, %1}, %2;" : "=f"(r.x), "=f"(r.y) : "l"(v));
    return r;
}

// ================= Kernel 1: A = f@W1a + pos@W1c + b1 ; Bt = f@W1b - pos@W1c ==============
// GEMM M=1024(rows bn) x N=512(j) x K=512(d), two weight halves share the feature tile.
// Tile: 32 rows x 64 cols, Kstep 32, 256 threads, 2x4 micro per thread per matrix.
__global__ __launch_bounds__(256) void k1_precompute(
    const float* __restrict__ f, const float* __restrict__ pos,
    const float* __restrict__ W1, const float* __restrict__ b1)
{
    __shared__ __align__(16) float fT[32][33];
    __shared__ __align__(16) float Wa[32][64];
    __shared__ __align__(16) float Wb[32][64];

    const int t    = threadIdx.x;
    const int j0   = blockIdx.x * 64;   // 8 blocks in x
    const int row0 = blockIdx.y * 32;   // 32 blocks in y
    const int tx   = t & 15;
    const int ty   = t >> 4;
    const int c0   = tx * 4;
    const int r0   = ty * 2;

    float accA[2][4] = {{0.f,0.f,0.f,0.f},{0.f,0.f,0.f,0.f}};
    float accB[2][4] = {{0.f,0.f,0.f,0.f},{0.f,0.f,0.f,0.f}};

    for (int d0 = 0; d0 < D; d0 += 32) {
        #pragma unroll
        for (int i = 0; i < 4; i++) {
            int idx = t + i * 256;
            int r = idx >> 5, dd = idx & 31;
            fT[r][dd] = f[(row0 + r) * D + d0 + dd];
        }
        #pragma unroll
        for (int i = 0; i < 8; i++) {
            int idx = t + i * 256;
            int dd = idx >> 6, j = idx & 63;
            Wa[dd][j] = W1[(d0 + dd) * D + j0 + j];
            Wb[dd][j] = W1[(D + d0 + dd) * D + j0 + j];
        }
        __syncthreads();
        #pragma unroll
        for (int dd = 0; dd < 32; dd++) {
            float f0 = fT[r0][dd];
            float f1 = fT[r0 + 1][dd];
            float4 wa4 = *reinterpret_cast<const float4*>(&Wa[dd][c0]);
            float4 wb4 = *reinterpret_cast<const float4*>(&Wb[dd][c0]);
            float wav[4] = {wa4.x, wa4.y, wa4.z, wa4.w};
            float wbv[4] = {wb4.x, wb4.y, wb4.z, wb4.w};
            #pragma unroll
            for (int j = 0; j < 4; j++) {
                accA[0][j] = fmaf(f0, wav[j], accA[0][j]);
                accA[1][j] = fmaf(f1, wav[j], accA[1][j]);
                accB[0][j] = fmaf(f0, wbv[j], accB[0][j]);
                accB[1][j] = fmaf(f1, wbv[j], accB[1][j]);
            }
        }
        __syncthreads();
    }

    // Epilogue: fold rank-1 position term + b1
    #pragma unroll
    for (int r = 0; r < 2; r++) {
        int row = row0 + r0 + r;
        float p0 = pos[row * 2 + 0];
        float p1 = pos[row * 2 + 1];
        #pragma unroll
        for (int j = 0; j < 4; j++) {
            int jj = j0 + c0 + j;
            float pcv = p0 * W1[(2 * D) * D + jj] + p1 * W1[(2 * D + 1) * D + jj];
            g_A[row * D + jj] = accA[r][j] + pcv + b1[jj];
            g_B[row * D + jj] = accB[r][j] - pcv;
        }
    }
}

// ================= Kernel 2: per (b,n): out[m,:] = relu(relu(A[n]+Bt[m]) @ W2 + b2) @ W3 + b3 ==========
// 1024 blocks (one per bn). 512 threads. Each block computes 128(m) x 256(l) with K=512 in 16-wide steps.
// Warp w owns m rows 8w..8w+7 (h reads are warp-broadcast). Lane tl owns l cols 8tl..8tl+7.
// Accumulators packed pairs along l -> fma.rn.f32x2 (2x fp32 rate).
__global__ __launch_bounds__(512, 1) void k2_main(
    const float* __restrict__ W2, const float* __restrict__ b2,
    const float* __restrict__ W3, const float* __restrict__ b3,
    float* __restrict__ out)
{
    __shared__ __align__(16) float aRow[D];
    __shared__ __align__(16) float hs[16][132];   // k-major, padded: rows 528B (16B-aligned)
    __shared__ __align__(16) float ws[16][L2DIM];

    const int bn = blockIdx.x;
    const int b  = bn >> 7;
    const int t  = threadIdx.x;
    const int tm = t >> 5;          // warp id = m-group
    const int tl = t & 31;          // lane    = l-group
    const int m0 = tm * 8;
    const int l0 = tl * 8;
    const float* Btbase = g_B + (size_t)b * NPAIR * D;

    aRow[t] = g_A[bn * D + t];      // 512 threads, 512 floats

    ull acc[8][4];                  // [m][l-pair] : 32 ulls = 64 regs
    #pragma unroll
    for (int i = 0; i < 8; i++)
        #pragma unroll
        for (int jp = 0; jp < 4; jp++) acc[i][jp] = pack2(0.f, 0.f);

    __syncthreads();

    for (int k0 = 0; k0 < D; k0 += 16) {
        // stage h tile: relu(aRow[k] + Bt[m][k]) -> hs[kk][m]
        #pragma unroll
        for (int i = 0; i < 4; i++) {
            int idx = t + i * 512;
            int kk = idx & 15, m = idx >> 4;
            float v = Btbase[m * D + k0 + kk] + aRow[k0 + kk];
            hs[kk][m] = fmaxf(v, 0.f);
        }
        // stage W2 tile
        #pragma unroll
        for (int i = 0; i < 8; i++) {
            int idx = t + i * 512;
            int kk = idx >> 8, l = idx & 255;
            ws[kk][l] = W2[(k0 + kk) * L2DIM + l];
        }
        __syncthreads();

        #pragma unroll
        for (int kk = 0; kk < 16; kk++) {
            float4 h0 = *reinterpret_cast<const float4*>(&hs[kk][m0]);      // broadcast in warp
            float4 h1 = *reinterpret_cast<const float4*>(&hs[kk][m0 + 4]);
            ulonglong2 wA = *reinterpret_cast<const ulonglong2*>(&ws[kk][l0]);
            ulonglong2 wB = *reinterpret_cast<const ulonglong2*>(&ws[kk][l0 + 4]);
            ull hh[8];
            hh[0] = pack2(h0.x, h0.x); hh[1] = pack2(h0.y, h0.y);
            hh[2] = pack2(h0.z, h0.z); hh[3] = pack2(h0.w, h0.w);
            hh[4] = pack2(h1.x, h1.x); hh[5] = pack2(h1.y, h1.y);
            hh[6] = pack2(h1.z, h1.z); hh[7] = pack2(h1.w, h1.w);
            #pragma unroll
            for (int i = 0; i < 8; i++) {
                ffma2(acc[i][0], hh[i], wA.x);
                ffma2(acc[i][1], hh[i], wA.y);
                ffma2(acc[i][2], hh[i], wB.x);
                ffma2(acc[i][3], hh[i], wB.y);
            }
        }
        __syncthreads();
    }

    // Epilogue: relu(acc + b2) @ W3, warp-reduce over l, + b3
    float b2v[8];
    float w3v[8][4];
    #pragma unroll
    for (int j = 0; j < 8; j++) {
        b2v[j] = b2[l0 + j];
        #pragma unroll
        for (int o = 0; o < 4; o++) w3v[j][o] = W3[(l0 + j) * 4 + o];
    }

    float vout[8][4];
    #pragma unroll
    for (int i = 0; i < 8; i++) {
        #pragma unroll
        for (int o = 0; o < 4; o++) vout[i][o] = 0.f;
        #pragma unroll
        for (int jp = 0; jp < 4; jp++) {
            float2 g2 = unpack2(acc[i][jp]);
            float g0 = fmaxf(g2.x + b2v[2 * jp + 0], 0.f);
            float g1 = fmaxf(g2.y + b2v[2 * jp + 1], 0.f);
            #pragma unroll
            for (int o = 0; o < 4; o++)
                vout[i][o] += g0 * w3v[2 * jp][o] + g1 * w3v[2 * jp + 1][o];
        }
    }

    #pragma unroll
    for (int off = 16; off > 0; off >>= 1) {
        #pragma unroll
        for (int i = 0; i < 8; i++)
            #pragma unroll
            for (int o = 0; o < 4; o++)
                vout[i][o] += __shfl_xor_sync(0xffffffffu, vout[i][o], off);
    }

    if (tl == 0) {
        #pragma unroll
        for (int i = 0; i < 8; i++) {
            #pragma unroll
            for (int o = 0; o < 4; o++)
                out[((size_t)bn * NPAIR + m0 + i) * 4 + o] = vout[i][o] + b3[o];
        }
    }
}

extern "C" void kernel_launch(void* const* d_in, const int* in_sizes, int n_in,
                              void* d_out, int out_size)
{
    const float* f   = (const float*)d_in[0];
    const float* pos = (const float*)d_in[1];
    const float* W1  = (const float*)d_in[2];
    const float* b1  = (const float*)d_in[3];
    const float* W2  = (const float*)d_in[4];
    const float* b2  = (const float*)d_in[5];
    const float* W3  = (const float*)d_in[6];
    const float* b3  = (const float*)d_in[7];
    float* out = (float*)d_out;

    k1_precompute<<<dim3(8, 32), 256>>>(f, pos, W1, b1);
    k2_main<<<1024, 512>>>(W2, b2, W3, b3, out);
}

// round 2
// speedup vs baseline: 1.1409x; 1.1409x over previous
#include <cuda_runtime.h>

#define D 512
#define BN 1024          // B*N = 8*128
#define NPAIR 128        // m per (b,n)
#define L2DIM 256        // W2 output width

typedef unsigned long long ull;

// Scratch (allocation-free rule: __device__ globals)
__device__ float g_A[BN * D];   // h1 + pc + b1   (indexed by n-row)
__device__ float g_B[BN * D];   // h2 - pc        (indexed by m-row)

// ---------------- f32x2 packed-FMA helpers ----------------
__device__ __forceinline__ void ffma2(ull &acc, ull a, ull b) {
    asm("fma.rn.f32x2 %0, %1, %2, %0;" : "+l"(acc) : "l"(a), "l"(b));
}
__device__ __forceinline__ ull pack2(float x, float y) {
    ull r;
    asm("mov.b64 %0, {%1, %2};" : "=l"(r) : "f"(x), "f"(y));
    return r;
}
__device__ __forceinline__ float2 unpack2(ull v) {
    float2 r;
    asm("mov.b64 {%0, %1}, %2;" : "=f"(r.x), "=f"(r.y) : "l"(v));
    return r;
}

// ================= Kernel 1: A = f@W1a + pos@W1c + b1 ; Bt = f@W1b - pos@W1c ==============
__global__ __launch_bounds__(256) void k1_precompute(
    const float* __restrict__ f, const float* __restrict__ pos,
    const float* __restrict__ W1, const float* __restrict__ b1)
{
    __shared__ __align__(16) float fT[32][33];
    __shared__ __align__(16) float Wa[32][64];
    __shared__ __align__(16) float Wb[32][64];

    const int t    = threadIdx.x;
    const int j0   = blockIdx.x * 64;
    const int row0 = blockIdx.y * 32;
    const int tx   = t & 15;
    const int ty   = t >> 4;
    const int c0   = tx * 4;
    const int r0   = ty * 2;

    float accA[2][4] = {{0.f,0.f,0.f,0.f},{0.f,0.f,0.f,0.f}};
    float accB[2][4] = {{0.f,0.f,0.f,0.f},{0.f,0.f,0.f,0.f}};

    for (int d0 = 0; d0 < D; d0 += 32) {
        #pragma unroll
        for (int i = 0; i < 4; i++) {
            int idx = t + i * 256;
            int r = idx >> 5, dd = idx & 31;
            fT[r][dd] = f[(row0 + r) * D + d0 + dd];
        }
        #pragma unroll
        for (int i = 0; i < 8; i++) {
            int idx = t + i * 256;
            int dd = idx >> 6, j = idx & 63;
            Wa[dd][j] = W1[(d0 + dd) * D + j0 + j];
            Wb[dd][j] = W1[(D + d0 + dd) * D + j0 + j];
        }
        __syncthreads();
        #pragma unroll
        for (int dd = 0; dd < 32; dd++) {
            float f0 = fT[r0][dd];
            float f1 = fT[r0 + 1][dd];
            float4 wa4 = *reinterpret_cast<const float4*>(&Wa[dd][c0]);
            float4 wb4 = *reinterpret_cast<const float4*>(&Wb[dd][c0]);
            float wav[4] = {wa4.x, wa4.y, wa4.z, wa4.w};
            float wbv[4] = {wb4.x, wb4.y, wb4.z, wb4.w};
            #pragma unroll
            for (int j = 0; j < 4; j++) {
                accA[0][j] = fmaf(f0, wav[j], accA[0][j]);
                accA[1][j] = fmaf(f1, wav[j], accA[1][j]);
                accB[0][j] = fmaf(f0, wbv[j], accB[0][j]);
                accB[1][j] = fmaf(f1, wbv[j], accB[1][j]);
            }
        }
        __syncthreads();
    }

    #pragma unroll
    for (int r = 0; r < 2; r++) {
        int row = row0 + r0 + r;
        float p0 = pos[row * 2 + 0];
        float p1 = pos[row * 2 + 1];
        #pragma unroll
        for (int j = 0; j < 4; j++) {
            int jj = j0 + c0 + j;
            float pcv = p0 * W1[(2 * D) * D + jj] + p1 * W1[(2 * D + 1) * D + jj];
            g_A[row * D + jj] = accA[r][j] + pcv + b1[jj];
            g_B[row * D + jj] = accB[r][j] - pcv;
        }
    }
}

// ================= Kernel 2 =================
// 1024 blocks (one per bn), 256 threads = 8 warps.
// Warp w owns m rows [16w, 16w+16). Lane tl owns l cols [8tl, 8tl+8).
// Per-thread tile: 16m x 8l in packed f32x2 accumulators (64 ull = 128 regs).
// Double-buffered k-tiles (kstep=16): LDG prefetch -> compute -> STS -> 1 sync.
__global__ __launch_bounds__(256, 1) void k2_main(
    const float* __restrict__ W2, const float* __restrict__ b2,
    const float* __restrict__ W3, const float* __restrict__ b3,
    float* __restrict__ out)
{
    __shared__ __align__(16) float aRow[D];
    __shared__ __align__(16) float hs[2][16][132];   // k-major h, padded row 528B
    __shared__ __align__(16) float ws[2][16][L2DIM];

    const int bn = blockIdx.x;
    const int b  = bn >> 7;
    const int t  = threadIdx.x;
    const int tm = t >> 5;          // warp id
    const int tl = t & 31;          // lane
    const int m0 = tm * 16;
    const int l0 = tl * 8;
    const float* Btbase = g_B + (size_t)b * NPAIR * D;

    // staging roles
    const int sm  = t >> 1;         // m row this thread stages (128 rows, 2 thr/row)
    const int sko = (t & 1) * 8;    // k sub-offset (0 or 8)

    aRow[t]       = g_A[bn * D + t];
    aRow[t + 256] = g_A[bn * D + t + 256];

    ull acc[16][4];
    #pragma unroll
    for (int i = 0; i < 16; i++)
        #pragma unroll
        for (int jp = 0; jp < 4; jp++) acc[i][jp] = pack2(0.f, 0.f);

    __syncthreads();   // aRow visible for staging

    float4 rB0, rB1;         // Bt prefetch (8 floats along k for row sm)
    float4 rW[4];            // W2 prefetch (16 floats)

    // ---- prefetch k0 = 0 ----
    rB0 = *reinterpret_cast<const float4*>(&Btbase[sm * D + sko]);
    rB1 = *reinterpret_cast<const float4*>(&Btbase[sm * D + sko + 4]);
    #pragma unroll
    for (int i = 0; i < 4; i++) {
        int idx = t + i * 256;
        int kk = idx >> 6, g = idx & 63;
        rW[i] = *reinterpret_cast<const float4*>(&W2[kk * L2DIM + g * 4]);
    }
    // ---- store tile 0 into buf 0 ----
    {
        float bt[8] = {rB0.x, rB0.y, rB0.z, rB0.w, rB1.x, rB1.y, rB1.z, rB1.w};
        #pragma unroll
        for (int j = 0; j < 8; j++)
            hs[0][sko + j][sm] = fmaxf(bt[j] + aRow[sko + j], 0.f);
        #pragma unroll
        for (int i = 0; i < 4; i++) {
            int idx = t + i * 256;
            int kk = idx >> 6, g = idx & 63;
            *reinterpret_cast<float4*>(&ws[0][kk][g * 4]) = rW[i];
        }
    }
    __syncthreads();

    int p = 0;
    for (int k0 = 0; k0 < D; k0 += 16) {
        const bool more = (k0 + 16 < D);
        // prefetch next tile
        if (more) {
            rB0 = *reinterpret_cast<const float4*>(&Btbase[sm * D + k0 + 16 + sko]);
            rB1 = *reinterpret_cast<const float4*>(&Btbase[sm * D + k0 + 16 + sko + 4]);
            #pragma unroll
            for (int i = 0; i < 4; i++) {
                int idx = t + i * 256;
                int kk = idx >> 6, g = idx & 63;
                rW[i] = *reinterpret_cast<const float4*>(&W2[(k0 + 16 + kk) * L2DIM + g * 4]);
            }
        }

        // compute on buffer p
        #pragma unroll
        for (int kk = 0; kk < 16; kk++) {
            float4 h0 = *reinterpret_cast<const float4*>(&hs[p][kk][m0]);       // warp-broadcast
            float4 h1 = *reinterpret_cast<const float4*>(&hs[p][kk][m0 + 4]);
            float4 h2 = *reinterpret_cast<const float4*>(&hs[p][kk][m0 + 8]);
            float4 h3 = *reinterpret_cast<const float4*>(&hs[p][kk][m0 + 12]);
            ulonglong2 wA = *reinterpret_cast<const ulonglong2*>(&ws[p][kk][l0]);
            ulonglong2 wB = *reinterpret_cast<const ulonglong2*>(&ws[p][kk][l0 + 4]);
            float hv[16] = {h0.x, h0.y, h0.z, h0.w, h1.x, h1.y, h1.z, h1.w,
                            h2.x, h2.y, h2.z, h2.w, h3.x, h3.y, h3.z, h3.w};
            #pragma unroll
            for (int i = 0; i < 16; i++) {
                ull hh = pack2(hv[i], hv[i]);
                ffma2(acc[i][0], hh, wA.x);
                ffma2(acc[i][1], hh, wA.y);
                ffma2(acc[i][2], hh, wB.x);
                ffma2(acc[i][3], hh, wB.y);
            }
        }

        // store next tile into buffer p^1
        if (more) {
            float bt[8] = {rB0.x, rB0.y, rB0.z, rB0.w, rB1.x, rB1.y, rB1.z, rB1.w};
            #pragma unroll
            for (int j = 0; j < 8; j++)
                hs[p ^ 1][sko + j][sm] = fmaxf(bt[j] + aRow[k0 + 16 + sko + j], 0.f);
            #pragma unroll
            for (int i = 0; i < 4; i++) {
                int idx = t + i * 256;
                int kk = idx >> 6, g = idx & 63;
                *reinterpret_cast<float4*>(&ws[p ^ 1][kk][g * 4]) = rW[i];
            }
        }
        __syncthreads();
        p ^= 1;
    }

    // Epilogue: relu(acc + b2) @ W3, warp-reduce over l (32 lanes cover all 256 l), + b3
    float b2v[8];
    float w3v[8][4];
    #pragma unroll
    for (int j = 0; j < 8; j++) {
        b2v[j] = b2[l0 + j];
        #pragma unroll
        for (int o = 0; o < 4; o++) w3v[j][o] = W3[(l0 + j) * 4 + o];
    }

    float vout[16][4];
    #pragma unroll
    for (int i = 0; i < 16; i++) {
        #pragma unroll
        for (int o = 0; o < 4; o++) vout[i][o] = 0.f;
        #pragma unroll
        for (int jp = 0; jp < 4; jp++) {
            float2 g2 = unpack2(acc[i][jp]);
            float g0 = fmaxf(g2.x + b2v[2 * jp + 0], 0.f);
            float g1 = fmaxf(g2.y + b2v[2 * jp + 1], 0.f);
            #pragma unroll
            for (int o = 0; o < 4; o++)
                vout[i][o] += g0 * w3v[2 * jp][o] + g1 * w3v[2 * jp + 1][o];
        }
    }

    #pragma unroll
    for (int off = 16; off > 0; off >>= 1) {
        #pragma unroll
        for (int i = 0; i < 16; i++)
            #pragma unroll
            for (int o = 0; o < 4; o++)
                vout[i][o] += __shfl_xor_sync(0xffffffffu, vout[i][o], off);
    }

    if (tl == 0) {
        #pragma unroll
        for (int i = 0; i < 16; i++) {
            #pragma unroll
            for (int o = 0; o < 4; o++)
                out[((size_t)bn * NPAIR + m0 + i) * 4 + o] = vout[i][o] + b3[o];
        }
    }
}

extern "C" void kernel_launch(void* const* d_in, const int* in_sizes, int n_in,
                              void* d_out, int out_size)
{
    const float* f   = (const float*)d_in[0];
    const float* pos = (const float*)d_in[1];
    const float* W1  = (const float*)d_in[2];
    const float* b1  = (const float*)d_in[3];
    const float* W2  = (const float*)d_in[4];
    const float* b2  = (const float*)d_in[5];
    const float* W3  = (const float*)d_in[6];
    const float* b3  = (const float*)d_in[7];
    float* out = (float*)d_out;

    k1_precompute<<<dim3(8, 32), 256>>>(f, pos, W1, b1);
    k2_main<<<1024, 256>>>(W2, b2, W3, b3, out);
}

// round 4
// speedup vs baseline: 2.8623x; 2.5088x over previous
#include <cuda_runtime.h>
#include <cstdint>

#define D 512
#define BN 1024          // B*N = 8*128
#define NPAIR 128        // m per (b,n)
#define L2DIM 256        // W2 output width
#define KC 32            // K per chunk
#define CHUNKS 16        // 512/32
#define HSTRIDE 36       // smem row stride (floats): (4m+k)%32 conflict-free fragments

// dyn smem layout (bytes)
#define OFF_AROW 0                  // 512*4 = 2048
#define OFF_B2   2048               // 1024
#define OFF_W3   3072               // 4096
#define OFF_PART 7168               // 128*4*4*4 = 8192
#define OFF_H    15360              // 2 * 128*36*4 = 36864
#define OFF_W    52224              // 2 * 256*36*4 = 73728
#define SMEM_TOTAL 125952

// Scratch (allocation-free rule: __device__ globals)
__device__ float g_A[BN * D];        // h1 + pc + b1   (indexed by n-row)
__device__ float g_B[BN * D];        // h2 - pc        (indexed by m-row)
__device__ float g_W2t[L2DIM * D];   // W2 transposed [l][k], tf32-rounded

// ---------------- helpers ----------------
__device__ __forceinline__ uint32_t smem_u32(const void* p) {
    uint32_t a;
    asm("{ .reg .u64 t; cvta.to.shared.u64 t, %1; cvt.u32.u64 %0, t; }" : "=r"(a) : "l"(p));
    return a;
}
__device__ __forceinline__ float tf32r(float x) {
    float r;
    asm("cvt.rna.tf32.f32 %0, %1;" : "=f"(r) : "f"(x));
    return r;
}
__device__ __forceinline__ void cp_async16(uint32_t dst, const void* src) {
    asm volatile("cp.async.cg.shared.global [%0], [%1], 16;" :: "r"(dst), "l"(src) : "memory");
}
#define CP_COMMIT() asm volatile("cp.async.commit_group;" ::: "memory")
#define CP_WAIT0()  asm volatile("cp.async.wait_group 0;" ::: "memory")

__device__ __forceinline__ void mma_tf32(float* d, const uint32_t* a, const uint32_t* b) {
    asm volatile(
        "mma.sync.aligned.m16n8k8.row.col.f32.tf32.tf32.f32 "
        "{%0,%1,%2,%3}, {%4,%5,%6,%7}, {%8,%9}, {%0,%1,%2,%3};"
        : "+f"(d[0]), "+f"(d[1]), "+f"(d[2]), "+f"(d[3])
        : "r"(a[0]), "r"(a[1]), "r"(a[2]), "r"(a[3]), "r"(b[0]), "r"(b[1]));
}

// ================= Kernel 0: W2t[l][k] = tf32(W2[k][l]) ==================
__global__ __launch_bounds__(256) void k0_w2t(const float* __restrict__ W2) {
    int idx = blockIdx.x * 256 + threadIdx.x;   // k*256 + l, coalesced read
    int k = idx >> 8, l = idx & 255;
    g_W2t[l * D + k] = tf32r(W2[idx]);
}

// ================= Kernel 1: A = f@W1a + pos@W1c + b1 ; Bt = f@W1b - pos@W1c ==============
__global__ __launch_bounds__(256) void k1_precompute(
    const float* __restrict__ f, const float* __restrict__ pos,
    const float* __restrict__ W1, const float* __restrict__ b1)
{
    __shared__ __align__(16) float fT[32][33];
    __shared__ __align__(16) float Wa[32][64];
    __shared__ __align__(16) float Wb[32][64];

    const int t    = threadIdx.x;
    const int j0   = blockIdx.x * 64;
    const int row0 = blockIdx.y * 32;
    const int tx   = t & 15;
    const int ty   = t >> 4;
    const int c0   = tx * 4;
    const int r0   = ty * 2;

    float accA[2][4] = {{0.f,0.f,0.f,0.f},{0.f,0.f,0.f,0.f}};
    float accB[2][4] = {{0.f,0.f,0.f,0.f},{0.f,0.f,0.f,0.f}};

    for (int d0 = 0; d0 < D; d0 += 32) {
        #pragma unroll
        for (int i = 0; i < 4; i++) {
            int idx = t + i * 256;
            int r = idx >> 5, dd = idx & 31;
            fT[r][dd] = f[(row0 + r) * D + d0 + dd];
        }
        #pragma unroll
        for (int i = 0; i < 8; i++) {
            int idx = t + i * 256;
            int dd = idx >> 6, j = idx & 63;
            Wa[dd][j] = W1[(d0 + dd) * D + j0 + j];
            Wb[dd][j] = W1[(D + d0 + dd) * D + j0 + j];
        }
        __syncthreads();
        #pragma unroll
        for (int dd = 0; dd < 32; dd++) {
            float f0 = fT[r0][dd];
            float f1 = fT[r0 + 1][dd];
            float4 wa4 = *reinterpret_cast<const float4*>(&Wa[dd][c0]);
            float4 wb4 = *reinterpret_cast<const float4*>(&Wb[dd][c0]);
            float wav[4] = {wa4.x, wa4.y, wa4.z, wa4.w};
            float wbv[4] = {wb4.x, wb4.y, wb4.z, wb4.w};
            #pragma unroll
            for (int j = 0; j < 4; j++) {
                accA[0][j] = fmaf(f0, wav[j], accA[0][j]);
                accA[1][j] = fmaf(f1, wav[j], accA[1][j]);
                accB[0][j] = fmaf(f0, wbv[j], accB[0][j]);
                accB[1][j] = fmaf(f1, wbv[j], accB[1][j]);
            }
        }
        __syncthreads();
    }

    #pragma unroll
    for (int r = 0; r < 2; r++) {
        int row = row0 + r0 + r;
        float p0 = pos[row * 2 + 0];
        float p1 = pos[row * 2 + 1];
        #pragma unroll
        for (int j = 0; j < 4; j++) {
            int jj = j0 + c0 + j;
            float pcv = p0 * W1[(2 * D) * D + jj] + p1 * W1[(2 * D + 1) * D + jj];
            g_A[row * D + jj] = accA[r][j] + pcv + b1[jj];
            g_B[row * D + jj] = accB[r][j] - pcv;
        }
    }
}

// ================= Kernel 2: tf32 mma.sync GEMM per (b,n) =================
// 1024 blocks, 256 thr = 8 warps (2m x 4l). Warp tile 64x64 = 4x8 m16n8k8 frags.
// K=512 in 16 chunks of 32; W2t via cp.async double-buffer; H staged tf32.
__global__ __launch_bounds__(256, 1) void k2_mma(
    const float* __restrict__ b2, const float* __restrict__ W3,
    const float* __restrict__ b3, float* __restrict__ out)
{
    extern __shared__ char smem[];
    const uint32_t sb = smem_u32(smem);
    float* aR   = (float*)(smem + OFF_AROW);
    float* b2s  = (float*)(smem + OFF_B2);
    float* w3s  = (float*)(smem + OFF_W3);
    float* part = (float*)(smem + OFF_PART);

    const int t = threadIdx.x, wid = t >> 5, lane = t & 31;
    const int wm = wid >> 2, wl = wid & 3;
    const int m0 = wm * 64, l0 = wl * 64;
    const int bn = blockIdx.x, b = bn >> 7;
    const float* Btb = g_B + (size_t)b * NPAIR * D;

    // prologue staging roles
    const int hm = t >> 1;             // H row (2 thr/row)
    const int hko = (t & 1) * 16;      // k sub-offset 0/16
    const int wrow = t >> 3;           // W row group base (coalesced: 8 lanes/row)
    const int wkq = t & 7;             // quad within 32k

    aR[t] = g_A[bn * D + t];
    aR[t + 256] = g_A[bn * D + 256 + t];
    b2s[t] = b2[t];
    #pragma unroll
    for (int i = 0; i < 4; i++) w3s[t + i * 256] = W3[t + i * 256];
    __syncthreads();

    float acc[4][8][4];
    #pragma unroll
    for (int mt = 0; mt < 4; mt++)
        #pragma unroll
        for (int nt = 0; nt < 8; nt++)
            #pragma unroll
            for (int c = 0; c < 4; c++) acc[mt][nt][c] = 0.f;

    // ---- chunk 0: cp.async W, LDG+STS H ----
    {
        uint32_t wdst = sb + OFF_W + (wrow * HSTRIDE + wkq * 4) * 4;
        #pragma unroll
        for (int i = 0; i < 8; i++)
            cp_async16(wdst + i * 32 * HSTRIDE * 4, &g_W2t[(wrow + 32 * i) * D + wkq * 4]);
        CP_COMMIT();

        float* hb = (float*)(smem + OFF_H);
        #pragma unroll
        for (int q = 0; q < 4; q++) {
            float4 v = *reinterpret_cast<const float4*>(&Btb[hm * D + hko + q * 4]);
            const float* ar = aR + hko + q * 4;
            float4 h;
            h.x = tf32r(fmaxf(v.x + ar[0], 0.f));
            h.y = tf32r(fmaxf(v.y + ar[1], 0.f));
            h.z = tf32r(fmaxf(v.z + ar[2], 0.f));
            h.w = tf32r(fmaxf(v.w + ar[3], 0.f));
            *reinterpret_cast<float4*>(&hb[hm * HSTRIDE + hko + q * 4]) = h;
        }
        CP_WAIT0();
        __syncthreads();
    }

    for (int c = 0; c < CHUNKS; c++) {
        const int buf = c & 1;
        const bool more = (c + 1 < CHUNKS);
        float4 rBt[4];

        if (more) {
            const int kn = (c + 1) * KC;
            uint32_t wdst = sb + OFF_W + ((buf ^ 1) * 256 * HSTRIDE + wrow * HSTRIDE + wkq * 4) * 4;
            #pragma unroll
            for (int i = 0; i < 8; i++)
                cp_async16(wdst + i * 32 * HSTRIDE * 4, &g_W2t[(wrow + 32 * i) * D + kn + wkq * 4]);
            CP_COMMIT();
            #pragma unroll
            for (int q = 0; q < 4; q++)
                rBt[q] = *reinterpret_cast<const float4*>(&Btb[hm * D + kn + hko + q * 4]);
        }

        // ---- compute chunk c ----
        const uint32_t* Hb = (const uint32_t*)(smem + OFF_H) + buf * 128 * HSTRIDE;
        const uint32_t* Wb = (const uint32_t*)(smem + OFF_W) + buf * 256 * HSTRIDE;
        const int lr = lane >> 2, lc = lane & 3;
        #pragma unroll
        for (int k8 = 0; k8 < 4; k8++) {
            const int kk = k8 * 8;
            uint32_t af[4][4];
            #pragma unroll
            for (int mt = 0; mt < 4; mt++) {
                const uint32_t* hp = Hb + (m0 + 16 * mt + lr) * HSTRIDE + kk + lc;
                af[mt][0] = hp[0];
                af[mt][1] = hp[8 * HSTRIDE];
                af[mt][2] = hp[4];
                af[mt][3] = hp[8 * HSTRIDE + 4];
            }
            uint32_t bf[8][2];
            #pragma unroll
            for (int nt = 0; nt < 8; nt++) {
                const uint32_t* bp = Wb + (l0 + 8 * nt + lr) * HSTRIDE + kk + lc;
                bf[nt][0] = bp[0];
                bf[nt][1] = bp[4];
            }
            #pragma unroll
            for (int mt = 0; mt < 4; mt++)
                #pragma unroll
                for (int nt = 0; nt < 8; nt++)
                    mma_tf32(acc[mt][nt], af[mt], bf[nt]);
        }

        if (more) {
            const int kn = (c + 1) * KC;
            float* hb = (float*)(smem + OFF_H) + (buf ^ 1) * 128 * HSTRIDE;
            #pragma unroll
            for (int q = 0; q < 4; q++) {
                const float* ar = aR + kn + hko + q * 4;
                float4 h;
                h.x = tf32r(fmaxf(rBt[q].x + ar[0], 0.f));
                h.y = tf32r(fmaxf(rBt[q].y + ar[1], 0.f));
                h.z = tf32r(fmaxf(rBt[q].z + ar[2], 0.f));
                h.w = tf32r(fmaxf(rBt[q].w + ar[3], 0.f));
                *reinterpret_cast<float4*>(&hb[hm * HSTRIDE + hko + q * 4]) = h;
            }
        }
        CP_WAIT0();
        __syncthreads();
    }

    // ---- epilogue: relu(acc + b2) @ W3, reduce l ----
    const int lr = lane >> 2, lc = lane & 3;
    #pragma unroll
    for (int mt = 0; mt < 4; mt++) {
        float o0[4] = {0.f, 0.f, 0.f, 0.f};
        float o1[4] = {0.f, 0.f, 0.f, 0.f};
        #pragma unroll
        for (int nt = 0; nt < 8; nt++) {
            int lcol = l0 + 8 * nt + 2 * lc;
            float vb0 = b2s[lcol], vb1 = b2s[lcol + 1];
            const float* w30 = &w3s[lcol * 4];
            const float* w31 = &w3s[(lcol + 1) * 4];
            float v00 = fmaxf(acc[mt][nt][0] + vb0, 0.f);
            float v01 = fmaxf(acc[mt][nt][1] + vb1, 0.f);
            float v10 = fmaxf(acc[mt][nt][2] + vb0, 0.f);
            float v11 = fmaxf(acc[mt][nt][3] + vb1, 0.f);
            #pragma unroll
            for (int o = 0; o < 4; o++) {
                o0[o] += v00 * w30[o] + v01 * w31[o];
                o1[o] += v10 * w30[o] + v11 * w31[o];
            }
        }
        #pragma unroll
        for (int off = 1; off <= 2; off <<= 1) {
            #pragma unroll
            for (int o = 0; o < 4; o++) {
                o0[o] += __shfl_xor_sync(0xffffffffu, o0[o], off);
                o1[o] += __shfl_xor_sync(0xffffffffu, o1[o], off);
            }
        }
        if (lc == 0) {
            int r0 = m0 + 16 * mt + lr;
            #pragma unroll
            for (int o = 0; o < 4; o++) {
                part[r0 * 16 + wl * 4 + o] = o0[o];
                part[(r0 + 8) * 16 + wl * 4 + o] = o1[o];
            }
        }
    }
    __syncthreads();

    if (t < 128) {
        float4 r;
        float s[4];
        #pragma unroll
        for (int o = 0; o < 4; o++) {
            s[o] = b3[o];
            #pragma unroll
            for (int w = 0; w < 4; w++) s[o] += part[t * 16 + w * 4 + o];
        }
        r.x = s[0]; r.y = s[1]; r.z = s[2]; r.w = s[3];
        *reinterpret_cast<float4*>(&out[((size_t)bn * NPAIR + t) * 4]) = r;
    }
}

extern "C" void kernel_launch(void* const* d_in, const int* in_sizes, int n_in,
                              void* d_out, int out_size)
{
    const float* f   = (const float*)d_in[0];
    const float* pos = (const float*)d_in[1];
    const float* W1  = (const float*)d_in[2];
    const float* b1  = (const float*)d_in[3];
    const float* W2  = (const float*)d_in[4];
    const float* b2  = (const float*)d_in[5];
    const float* W3  = (const float*)d_in[6];
    const float* b3  = (const float*)d_in[7];
    float* out = (float*)d_out;

    cudaFuncSetAttribute(k2_mma, cudaFuncAttributeMaxDynamicSharedMemorySize, SMEM_TOTAL);

    k0_w2t<<<512, 256>>>(W2);
    k1_precompute<<<dim3(8, 32), 256>>>(f, pos, W1, b1);
    k2_mma<<<1024, 256, SMEM_TOTAL>>>(b2, W3, b3, out);
}

// round 5
// speedup vs baseline: 2.9882x; 1.0440x over previous
#include <cuda_runtime.h>
#include <cstdint>

#define D 512
#define BN 1024          // B*N = 8*128
#define NPAIR 128        // m per (b,n)
#define L2DIM 256        // W2 output width
#define KC 32            // K per chunk
#define CHUNKS 16        // 512/32
#define HSTRIDE 36       // smem row stride (floats): (4m+k)%32 conflict-free fragments

// dyn smem layout (bytes)
#define OFF_AROW 0                  // 512*4 = 2048
#define OFF_B2   2048               // 1024
#define OFF_W3   3072               // 4096
#define OFF_PART 7168               // 128*16*4 = 8192
#define OFF_H    15360              // 2 * 128*36*4 = 36864
#define OFF_W    52224              // 2 * 256*36*4 = 73728
#define SMEM_TOTAL 125952

// Scratch (allocation-free rule: __device__ globals)
__device__ float g_A[BN * D];        // h1 + pc + b1   (indexed by n-row)
__device__ float g_B[BN * D];        // h2 - pc        (indexed by m-row)
__device__ float g_W2t[L2DIM * D];   // W2 transposed [l][k], tf32-rounded

// ---------------- helpers ----------------
__device__ __forceinline__ uint32_t smem_u32(const void* p) {
    uint32_t a;
    asm("{ .reg .u64 t; cvta.to.shared.u64 t, %1; cvt.u32.u64 %0, t; }" : "=r"(a) : "l"(p));
    return a;
}
__device__ __forceinline__ float tf32r(float x) {
    float r;
    asm("cvt.rna.tf32.f32 %0, %1;" : "=f"(r) : "f"(x));
    return r;
}
__device__ __forceinline__ void cp_async16(uint32_t dst, const void* src) {
    asm volatile("cp.async.cg.shared.global [%0], [%1], 16;" :: "r"(dst), "l"(src) : "memory");
}
#define CP_COMMIT() asm volatile("cp.async.commit_group;" ::: "memory")
#define CP_WAIT0()  asm volatile("cp.async.wait_group 0;" ::: "memory")

__device__ __forceinline__ void mma_tf32(float* d, const uint32_t* a, const uint32_t* b) {
    asm volatile(
        "mma.sync.aligned.m16n8k8.row.col.f32.tf32.tf32.f32 "
        "{%0,%1,%2,%3}, {%4,%5,%6,%7}, {%8,%9}, {%0,%1,%2,%3};"
        : "+f"(d[0]), "+f"(d[1]), "+f"(d[2]), "+f"(d[3])
        : "r"(a[0]), "r"(a[1]), "r"(a[2]), "r"(a[3]), "r"(b[0]), "r"(b[1]));
}

// ================= Kernel 0: W2t[l][k] = tf32(W2[k][l]) ==================
__global__ __launch_bounds__(256) void k0_w2t(const float* __restrict__ W2) {
    int idx = blockIdx.x * 256 + threadIdx.x;   // k*256 + l, coalesced read
    int k = idx >> 8, l = idx & 255;
    g_W2t[l * D + k] = tf32r(W2[idx]);
}

// ================= Kernel 1: A = f@W1a + pos@W1c + b1 ; Bt = f@W1b - pos@W1c ==============
__global__ __launch_bounds__(256) void k1_precompute(
    const float* __restrict__ f, const float* __restrict__ pos,
    const float* __restrict__ W1, const float* __restrict__ b1)
{
    __shared__ __align__(16) float fT[32][33];
    __shared__ __align__(16) float Wa[32][64];
    __shared__ __align__(16) float Wb[32][64];

    const int t    = threadIdx.x;
    const int j0   = blockIdx.x * 64;
    const int row0 = blockIdx.y * 32;
    const int tx   = t & 15;
    const int ty   = t >> 4;
    const int c0   = tx * 4;
    const int r0   = ty * 2;

    float accA[2][4] = {{0.f,0.f,0.f,0.f},{0.f,0.f,0.f,0.f}};
    float accB[2][4] = {{0.f,0.f,0.f,0.f},{0.f,0.f,0.f,0.f}};

    for (int d0 = 0; d0 < D; d0 += 32) {
        #pragma unroll
        for (int i = 0; i < 4; i++) {
            int idx = t + i * 256;
            int r = idx >> 5, dd = idx & 31;
            fT[r][dd] = f[(row0 + r) * D + d0 + dd];
        }
        #pragma unroll
        for (int i = 0; i < 8; i++) {
            int idx = t + i * 256;
            int dd = idx >> 6, j = idx & 63;
            Wa[dd][j] = W1[(d0 + dd) * D + j0 + j];
            Wb[dd][j] = W1[(D + d0 + dd) * D + j0 + j];
        }
        __syncthreads();
        #pragma unroll
        for (int dd = 0; dd < 32; dd++) {
            float f0 = fT[r0][dd];
            float f1 = fT[r0 + 1][dd];
            float4 wa4 = *reinterpret_cast<const float4*>(&Wa[dd][c0]);
            float4 wb4 = *reinterpret_cast<const float4*>(&Wb[dd][c0]);
            float wav[4] = {wa4.x, wa4.y, wa4.z, wa4.w};
            float wbv[4] = {wb4.x, wb4.y, wb4.z, wb4.w};
            #pragma unroll
            for (int j = 0; j < 4; j++) {
                accA[0][j] = fmaf(f0, wav[j], accA[0][j]);
                accA[1][j] = fmaf(f1, wav[j], accA[1][j]);
                accB[0][j] = fmaf(f0, wbv[j], accB[0][j]);
                accB[1][j] = fmaf(f1, wbv[j], accB[1][j]);
            }
        }
        __syncthreads();
    }

    #pragma unroll
    for (int r = 0; r < 2; r++) {
        int row = row0 + r0 + r;
        float p0 = pos[row * 2 + 0];
        float p1 = pos[row * 2 + 1];
        #pragma unroll
        for (int j = 0; j < 4; j++) {
            int jj = j0 + c0 + j;
            float pcv = p0 * W1[(2 * D) * D + jj] + p1 * W1[(2 * D + 1) * D + jj];
            g_A[row * D + jj] = accA[r][j] + pcv + b1[jj];
            g_B[row * D + jj] = accB[r][j] - pcv;
        }
    }
}

// ================= Kernel 2: tf32 mma.sync GEMM per (b,n) =================
// 1024 blocks, 512 thr = 16 warps (4m x 4l). Warp tile 32x64 = 2x8 m16n8k8 frags.
// K=512 in 16 chunks of 32; W2t via cp.async double-buffer; H staged tf32.
__global__ __launch_bounds__(512, 1) void k2_mma(
    const float* __restrict__ b2, const float* __restrict__ W3,
    const float* __restrict__ b3, float* __restrict__ out)
{
    extern __shared__ char smem[];
    const uint32_t sb = smem_u32(smem);
    float* aR   = (float*)(smem + OFF_AROW);
    float* b2s  = (float*)(smem + OFF_B2);
    float* w3s  = (float*)(smem + OFF_W3);
    float* part = (float*)(smem + OFF_PART);

    const int t = threadIdx.x, wid = t >> 5, lane = t & 31;
    const int wm = wid >> 2, wl = wid & 3;
    const int m0 = wm * 32, l0 = wl * 64;
    const int bn = blockIdx.x, b = bn >> 7;
    const float* Btb = g_B + (size_t)b * NPAIR * D;

    // staging roles
    const int hm  = t >> 2;            // H row (4 thr/row, 128 rows)
    const int hko = (t & 3) * 8;       // k sub-offset 0/8/16/24
    const int wrow = t >> 3;           // W row base (64 rows/pass, 4 passes)
    const int wkq  = t & 7;            // float4 quad within 32k

    if (t < 256) { b2s[t] = b2[t]; }
    else { int u = t - 256; aR[u + 256] = g_A[bn * D + 256 + u]; }
    if (t < 256) aR[t] = g_A[bn * D + t];
    #pragma unroll
    for (int i = 0; i < 2; i++) w3s[t + i * 512] = W3[t + i * 512];
    __syncthreads();

    float acc[2][8][4];
    #pragma unroll
    for (int mt = 0; mt < 2; mt++)
        #pragma unroll
        for (int nt = 0; nt < 8; nt++)
            #pragma unroll
            for (int c = 0; c < 4; c++) acc[mt][nt][c] = 0.f;

    // ---- chunk 0: cp.async W, LDG+STS H ----
    {
        uint32_t wdst = sb + OFF_W + (wrow * HSTRIDE + wkq * 4) * 4;
        #pragma unroll
        for (int i = 0; i < 4; i++)
            cp_async16(wdst + i * 64 * HSTRIDE * 4, &g_W2t[(wrow + 64 * i) * D + wkq * 4]);
        CP_COMMIT();

        float* hb = (float*)(smem + OFF_H);
        #pragma unroll
        for (int q = 0; q < 2; q++) {
            float4 v = *reinterpret_cast<const float4*>(&Btb[hm * D + hko + q * 4]);
            const float* ar = aR + hko + q * 4;
            float4 h;
            h.x = tf32r(fmaxf(v.x + ar[0], 0.f));
            h.y = tf32r(fmaxf(v.y + ar[1], 0.f));
            h.z = tf32r(fmaxf(v.z + ar[2], 0.f));
            h.w = tf32r(fmaxf(v.w + ar[3], 0.f));
            *reinterpret_cast<float4*>(&hb[hm * HSTRIDE + hko + q * 4]) = h;
        }
        CP_WAIT0();
        __syncthreads();
    }

    const int lr = lane >> 2, lc = lane & 3;

    for (int c = 0; c < CHUNKS; c++) {
        const int buf = c & 1;
        const bool more = (c + 1 < CHUNKS);
        float4 rBt[2];

        if (more) {
            const int kn = (c + 1) * KC;
            uint32_t wdst = sb + OFF_W + ((buf ^ 1) * 256 * HSTRIDE + wrow * HSTRIDE + wkq * 4) * 4;
            #pragma unroll
            for (int i = 0; i < 4; i++)
                cp_async16(wdst + i * 64 * HSTRIDE * 4, &g_W2t[(wrow + 64 * i) * D + kn + wkq * 4]);
            CP_COMMIT();
            #pragma unroll
            for (int q = 0; q < 2; q++)
                rBt[q] = *reinterpret_cast<const float4*>(&Btb[hm * D + kn + hko + q * 4]);
        }

        // ---- compute chunk c ----
        const uint32_t* Hb = (const uint32_t*)(smem + OFF_H) + buf * 128 * HSTRIDE;
        const uint32_t* Wb = (const uint32_t*)(smem + OFF_W) + buf * 256 * HSTRIDE;
        #pragma unroll
        for (int k8 = 0; k8 < 4; k8++) {
            const int kk = k8 * 8;
            uint32_t af[2][4];
            #pragma unroll
            for (int mt = 0; mt < 2; mt++) {
                const uint32_t* hp = Hb + (m0 + 16 * mt + lr) * HSTRIDE + kk + lc;
                af[mt][0] = hp[0];
                af[mt][1] = hp[8 * HSTRIDE];
                af[mt][2] = hp[4];
                af[mt][3] = hp[8 * HSTRIDE + 4];
            }
            uint32_t bf[8][2];
            #pragma unroll
            for (int nt = 0; nt < 8; nt++) {
                const uint32_t* bp = Wb + (l0 + 8 * nt + lr) * HSTRIDE + kk + lc;
                bf[nt][0] = bp[0];
                bf[nt][1] = bp[4];
            }
            #pragma unroll
            for (int mt = 0; mt < 2; mt++)
                #pragma unroll
                for (int nt = 0; nt < 8; nt++)
                    mma_tf32(acc[mt][nt], af[mt], bf[nt]);
        }

        if (more) {
            const int kn = (c + 1) * KC;
            float* hb = (float*)(smem + OFF_H) + (buf ^ 1) * 128 * HSTRIDE;
            #pragma unroll
            for (int q = 0; q < 2; q++) {
                const float* ar = aR + kn + hko + q * 4;
                float4 h;
                h.x = tf32r(fmaxf(rBt[q].x + ar[0], 0.f));
                h.y = tf32r(fmaxf(rBt[q].y + ar[1], 0.f));
                h.z = tf32r(fmaxf(rBt[q].z + ar[2], 0.f));
                h.w = tf32r(fmaxf(rBt[q].w + ar[3], 0.f));
                *reinterpret_cast<float4*>(&hb[hm * HSTRIDE + hko + q * 4]) = h;
            }
        }
        CP_WAIT0();
        __syncthreads();
    }

    // ---- epilogue: relu(acc + b2) @ W3, reduce over l-warps ----
    #pragma unroll
    for (int mt = 0; mt < 2; mt++) {
        float o0[4] = {0.f, 0.f, 0.f, 0.f};
        float o1[4] = {0.f, 0.f, 0.f, 0.f};
        #pragma unroll
        for (int nt = 0; nt < 8; nt++) {
            int lcol = l0 + 8 * nt + 2 * lc;
            float vb0 = b2s[lcol], vb1 = b2s[lcol + 1];
            const float* w30 = &w3s[lcol * 4];
            const float* w31 = &w3s[(lcol + 1) * 4];
            float v00 = fmaxf(acc[mt][nt][0] + vb0, 0.f);
            float v01 = fmaxf(acc[mt][nt][1] + vb1, 0.f);
            float v10 = fmaxf(acc[mt][nt][2] + vb0, 0.f);
            float v11 = fmaxf(acc[mt][nt][3] + vb1, 0.f);
            #pragma unroll
            for (int o = 0; o < 4; o++) {
                o0[o] += v00 * w30[o] + v01 * w31[o];
                o1[o] += v10 * w30[o] + v11 * w31[o];
            }
        }
        #pragma unroll
        for (int off = 1; off <= 2; off <<= 1) {
            #pragma unroll
            for (int o = 0; o < 4; o++) {
                o0[o] += __shfl_xor_sync(0xffffffffu, o0[o], off);
                o1[o] += __shfl_xor_sync(0xffffffffu, o1[o], off);
            }
        }
        if (lc == 0) {
            int r0 = m0 + 16 * mt + lr;
            #pragma unroll
            for (int o = 0; o < 4; o++) {
                part[r0 * 16 + wl * 4 + o] = o0[o];
                part[(r0 + 8) * 16 + wl * 4 + o] = o1[o];
            }
        }
    }
    __syncthreads();

    if (t < 128) {
        float4 r;
        float s[4];
        #pragma unroll
        for (int o = 0; o < 4; o++) {
            s[o] = b3[o];
            #pragma unroll
            for (int w = 0; w < 4; w++) s[o] += part[t * 16 + w * 4 + o];
        }
        r.x = s[0]; r.y = s[1]; r.z = s[2]; r.w = s[3];
        *reinterpret_cast<float4*>(&out[((size_t)bn * NPAIR + t) * 4]) = r;
    }
}

extern "C" void kernel_launch(void* const* d_in, const int* in_sizes, int n_in,
                              void* d_out, int out_size)
{
    const float* f   = (const float*)d_in[0];
    const float* pos = (const float*)d_in[1];
    const float* W1  = (const float*)d_in[2];
    const float* b1  = (const float*)d_in[3];
    const float* W2  = (const float*)d_in[4];
    const float* b2  = (const float*)d_in[5];
    const float* W3  = (const float*)d_in[6];
    const float* b3  = (const float*)d_in[7];
    float* out = (float*)d_out;

    cudaFuncSetAttribute(k2_mma, cudaFuncAttributeMaxDynamicSharedMemorySize, SMEM_TOTAL);

    k0_w2t<<<512, 256>>>(W2);
    k1_precompute<<<dim3(8, 32), 256>>>(f, pos, W1, b1);
    k2_mma<<<1024, 512, SMEM_TOTAL>>>(b2, W3, b3, out);
}

// round 6
// speedup vs baseline: 3.9743x; 1.3300x over previous
#include <cuda_runtime.h>
#include <cuda_fp16.h>
#include <cstdint>

#define D 512
#define BN 1024          // B*N = 8*128
#define NPAIR 128        // m per (b,n)
#define L2DIM 256        // W2 output width
#define KC 32            // K per chunk
#define CHUNKS 16        // 512/32
#define HROWB 80         // H smem row stride bytes (5*16B -> conflict-free ldmatrix)
#define WROWB 80         // W smem row stride bytes

// dyn smem layout (bytes)
#define OFF_AROW 0                   // 512*4 = 2048
#define OFF_B2   2048                // 1024
#define OFF_W3   3072                // 4096
#define OFF_PART 7168                // 128*16*4 = 8192
#define OFF_H    15360               // 2 * 128*80 = 20480
#define OFF_W    35840               // 2 * 256*80 = 40960
#define SMEM_TOTAL 76800

// Scratch (allocation-free rule: __device__ globals)
__device__ float  g_A[BN * D];        // h1 + pc + b1   (indexed by n-row)
__device__ float  g_B[BN * D];        // h2 - pc        (indexed by m-row)
__device__ __half g_W2h[L2DIM * D];   // W2 transposed [l][k], fp16

// ---------------- helpers ----------------
__device__ __forceinline__ uint32_t smem_u32(const void* p) {
    uint32_t a;
    asm("{ .reg .u64 t; cvta.to.shared.u64 t, %1; cvt.u32.u64 %0, t; }" : "=r"(a) : "l"(p));
    return a;
}
__device__ __forceinline__ void cp_async16(uint32_t dst, const void* src) {
    asm volatile("cp.async.cg.shared.global [%0], [%1], 16;" :: "r"(dst), "l"(src) : "memory");
}
#define CP_COMMIT() asm volatile("cp.async.commit_group;" ::: "memory")
#define CP_WAIT0()  asm volatile("cp.async.wait_group 0;" ::: "memory")

__device__ __forceinline__ void ldsm4(uint32_t* r, uint32_t addr) {
    asm volatile("ldmatrix.sync.aligned.m8n8.x4.shared.b16 {%0,%1,%2,%3}, [%4];"
        : "=r"(r[0]), "=r"(r[1]), "=r"(r[2]), "=r"(r[3]) : "r"(addr));
}
__device__ __forceinline__ void mma_f16(float* d, const uint32_t* a, const uint32_t* b) {
    asm volatile(
        "mma.sync.aligned.m16n8k16.row.col.f32.f16.f16.f32 "
        "{%0,%1,%2,%3}, {%4,%5,%6,%7}, {%8,%9}, {%0,%1,%2,%3};"
        : "+f"(d[0]), "+f"(d[1]), "+f"(d[2]), "+f"(d[3])
        : "r"(a[0]), "r"(a[1]), "r"(a[2]), "r"(a[3]), "r"(b[0]), "r"(b[1]));
}
__device__ __forceinline__ uint32_t packh2(float x, float y) {
    __half2 h = __floats2half2_rn(x, y);
    return *reinterpret_cast<uint32_t*>(&h);
}

// ================= Kernel 1 (merged): =================
// blocks y<32: A = f@W1a + pos@W1c + b1 ; Bt = f@W1b - pos@W1c
// blocks y>=32: W2h[l][k] = fp16(W2[k][l])  (512 transpose blocks)
__global__ __launch_bounds__(256) void k1_precompute(
    const float* __restrict__ f, const float* __restrict__ pos,
    const float* __restrict__ W1, const float* __restrict__ b1,
    const float* __restrict__ W2)
{
    if (blockIdx.y >= 32) {
        int tb = (blockIdx.y - 32) * 8 + blockIdx.x;     // 0..511
        int idx = tb * 256 + threadIdx.x;                // k*256 + l, coalesced read
        int k = idx >> 8, l = idx & 255;
        g_W2h[l * D + k] = __float2half_rn(W2[idx]);
        return;
    }

    __shared__ __align__(16) float fT[32][33];
    __shared__ __align__(16) float Wa[32][64];
    __shared__ __align__(16) float Wb[32][64];

    const int t    = threadIdx.x;
    const int j0   = blockIdx.x * 64;
    const int row0 = blockIdx.y * 32;
    const int tx   = t & 15;
    const int ty   = t >> 4;
    const int c0   = tx * 4;
    const int r0   = ty * 2;

    float accA[2][4] = {{0.f,0.f,0.f,0.f},{0.f,0.f,0.f,0.f}};
    float accB[2][4] = {{0.f,0.f,0.f,0.f},{0.f,0.f,0.f,0.f}};

    for (int d0 = 0; d0 < D; d0 += 32) {
        #pragma unroll
        for (int i = 0; i < 4; i++) {
            int idx = t + i * 256;
            int r = idx >> 5, dd = idx & 31;
            fT[r][dd] = f[(row0 + r) * D + d0 + dd];
        }
        #pragma unroll
        for (int i = 0; i < 8; i++) {
            int idx = t + i * 256;
            int dd = idx >> 6, j = idx & 63;
            Wa[dd][j] = W1[(d0 + dd) * D + j0 + j];
            Wb[dd][j] = W1[(D + d0 + dd) * D + j0 + j];
        }
        __syncthreads();
        #pragma unroll
        for (int dd = 0; dd < 32; dd++) {
            float f0 = fT[r0][dd];
            float f1 = fT[r0 + 1][dd];
            float4 wa4 = *reinterpret_cast<const float4*>(&Wa[dd][c0]);
            float4 wb4 = *reinterpret_cast<const float4*>(&Wb[dd][c0]);
            float wav[4] = {wa4.x, wa4.y, wa4.z, wa4.w};
            float wbv[4] = {wb4.x, wb4.y, wb4.z, wb4.w};
            #pragma unroll
            for (int j = 0; j < 4; j++) {
                accA[0][j] = fmaf(f0, wav[j], accA[0][j]);
                accA[1][j] = fmaf(f1, wav[j], accA[1][j]);
                accB[0][j] = fmaf(f0, wbv[j], accB[0][j]);
                accB[1][j] = fmaf(f1, wbv[j], accB[1][j]);
            }
        }
        __syncthreads();
    }

    #pragma unroll
    for (int r = 0; r < 2; r++) {
        int row = row0 + r0 + r;
        float p0 = pos[row * 2 + 0];
        float p1 = pos[row * 2 + 1];
        #pragma unroll
        for (int j = 0; j < 4; j++) {
            int jj = j0 + c0 + j;
            float pcv = p0 * W1[(2 * D) * D + jj] + p1 * W1[(2 * D + 1) * D + jj];
            g_A[row * D + jj] = accA[r][j] + pcv + b1[jj];
            g_B[row * D + jj] = accB[r][j] - pcv;
        }
    }
}

// ================= Kernel 2: fp16 mma.sync GEMM per (b,n) =================
// 1024 blocks, 512 thr = 16 warps (4m x 4l). Warp tile 32x64 = 2x8 m16n8k16 frags.
// K=512 in 16 chunks of 32 (2 k-steps of 16). ldmatrix fragments, 80B-stride smem
// (conflict-free), cp.async W double-buffer, H computed fp32 -> fp16.
__global__ __launch_bounds__(512, 1) void k2_mma(
    const float* __restrict__ b2, const float* __restrict__ W3,
    const float* __restrict__ b3, float* __restrict__ out)
{
    extern __shared__ char smem[];
    const uint32_t sb = smem_u32(smem);
    float* aR   = (float*)(smem + OFF_AROW);
    float* b2s  = (float*)(smem + OFF_B2);
    float* w3s  = (float*)(smem + OFF_W3);
    float* part = (float*)(smem + OFF_PART);

    const int t = threadIdx.x, wid = t >> 5, lane = t & 31;
    const int wm = wid >> 2, wl = wid & 3;
    const int m0 = wm * 32, l0 = wl * 64;
    const int bn = blockIdx.x, b = bn >> 7;
    const float* Btb = g_B + (size_t)b * NPAIR * D;

    // staging roles
    const int hrow = t >> 2;            // H row (4 thr/row, 128 rows)
    const int hch  = t & 3;             // 16B chunk (8 fp16 = 8 k)
    const int wrow = t >> 1;            // W row (2 thr/row, 256 rows)
    const int wch  = (t & 1) * 2;       // chunk base (2 chunks of 16B each thread)

    if (t < 256) { b2s[t] = b2[t]; aR[t] = g_A[bn * D + t]; }
    else { int u = t - 256; aR[u + 256] = g_A[bn * D + 256 + u]; }
    #pragma unroll
    for (int i = 0; i < 2; i++) w3s[t + i * 512] = W3[t + i * 512];
    __syncthreads();

    float acc[2][8][4];
    #pragma unroll
    for (int mt = 0; mt < 2; mt++)
        #pragma unroll
        for (int nt = 0; nt < 8; nt++)
            #pragma unroll
            for (int c = 0; c < 4; c++) acc[mt][nt][c] = 0.f;

    // ---- chunk 0: cp.async W, LDG+STS H ----
    {
        uint32_t wdst = sb + OFF_W + wrow * WROWB + wch * 16;
        cp_async16(wdst,      &g_W2h[wrow * D + wch * 8]);
        cp_async16(wdst + 16, &g_W2h[wrow * D + wch * 8 + 8]);
        CP_COMMIT();

        float4 v0 = *reinterpret_cast<const float4*>(&Btb[hrow * D + hch * 8]);
        float4 v1 = *reinterpret_cast<const float4*>(&Btb[hrow * D + hch * 8 + 4]);
        const float* ar = aR + hch * 8;
        uint32_t hp[4];
        hp[0] = packh2(fmaxf(v0.x + ar[0], 0.f), fmaxf(v0.y + ar[1], 0.f));
        hp[1] = packh2(fmaxf(v0.z + ar[2], 0.f), fmaxf(v0.w + ar[3], 0.f));
        hp[2] = packh2(fmaxf(v1.x + ar[4], 0.f), fmaxf(v1.y + ar[5], 0.f));
        hp[3] = packh2(fmaxf(v1.z + ar[6], 0.f), fmaxf(v1.w + ar[7], 0.f));
        *reinterpret_cast<uint4*>(smem + OFF_H + hrow * HROWB + hch * 16) =
            make_uint4(hp[0], hp[1], hp[2], hp[3]);
        CP_WAIT0();
        __syncthreads();
    }

    const int fr = lane & 15;            // ldmatrix row within 16
    const int fc = lane >> 4;            // ldmatrix 16B-chunk (0/1)

    for (int c = 0; c < CHUNKS; c++) {
        const int buf = c & 1;
        const bool more = (c + 1 < CHUNKS);
        float4 rB0, rB1;

        if (more) {
            const int kn = (c + 1) * KC;
            uint32_t wdst = sb + OFF_W + (buf ^ 1) * 256 * WROWB + wrow * WROWB + wch * 16;
            cp_async16(wdst,      &g_W2h[wrow * D + kn + wch * 8]);
            cp_async16(wdst + 16, &g_W2h[wrow * D + kn + wch * 8 + 8]);
            CP_COMMIT();
            rB0 = *reinterpret_cast<const float4*>(&Btb[hrow * D + kn + hch * 8]);
            rB1 = *reinterpret_cast<const float4*>(&Btb[hrow * D + kn + hch * 8 + 4]);
        }

        // ---- compute chunk c: 2 k-steps of 16 ----
        const uint32_t Hb = sb + OFF_H + buf * 128 * HROWB;
        const uint32_t Wb = sb + OFF_W + buf * 256 * WROWB;
        #pragma unroll
        for (int ks = 0; ks < 2; ks++) {
            const int kb = ks * 32 + fc * 16;   // byte offset within row
            uint32_t af[2][4];
            #pragma unroll
            for (int mt = 0; mt < 2; mt++)
                ldsm4(af[mt], Hb + (m0 + mt * 16 + fr) * HROWB + kb);
            uint32_t bf[4][4];
            #pragma unroll
            for (int g = 0; g < 4; g++)
                ldsm4(bf[g], Wb + (l0 + g * 16 + fr) * WROWB + kb);
            #pragma unroll
            for (int mt = 0; mt < 2; mt++)
                #pragma unroll
                for (int g = 0; g < 4; g++) {
                    uint32_t blo[2] = {bf[g][0], bf[g][2]};   // n rows g*16+0..7
                    uint32_t bhi[2] = {bf[g][1], bf[g][3]};   // n rows g*16+8..15
                    mma_f16(acc[mt][2 * g],     af[mt], blo);
                    mma_f16(acc[mt][2 * g + 1], af[mt], bhi);
                }
        }

        if (more) {
            const float* ar = aR + (c + 1) * KC + hch * 8;
            uint32_t hp[4];
            hp[0] = packh2(fmaxf(rB0.x + ar[0], 0.f), fmaxf(rB0.y + ar[1], 0.f));
            hp[1] = packh2(fmaxf(rB0.z + ar[2], 0.f), fmaxf(rB0.w + ar[3], 0.f));
            hp[2] = packh2(fmaxf(rB1.x + ar[4], 0.f), fmaxf(rB1.y + ar[5], 0.f));
            hp[3] = packh2(fmaxf(rB1.z + ar[6], 0.f), fmaxf(rB1.w + ar[7], 0.f));
            *reinterpret_cast<uint4*>(smem + OFF_H + (buf ^ 1) * 128 * HROWB + hrow * HROWB + hch * 16) =
                make_uint4(hp[0], hp[1], hp[2], hp[3]);
        }
        CP_WAIT0();
        __syncthreads();
    }

    // ---- epilogue: relu(acc + b2) @ W3, reduce over l-warps ----
    const int lr = lane >> 2, lc = lane & 3;
    #pragma unroll
    for (int mt = 0; mt < 2; mt++) {
        float o0[4] = {0.f, 0.f, 0.f, 0.f};
        float o1[4] = {0.f, 0.f, 0.f, 0.f};
        #pragma unroll
        for (int nt = 0; nt < 8; nt++) {
            int lcol = l0 + 8 * nt + 2 * lc;
            float vb0 = b2s[lcol], vb1 = b2s[lcol + 1];
            const float* w30 = &w3s[lcol * 4];
            const float* w31 = &w3s[(lcol + 1) * 4];
            float v00 = fmaxf(acc[mt][nt][0] + vb0, 0.f);
            float v01 = fmaxf(acc[mt][nt][1] + vb1, 0.f);
            float v10 = fmaxf(acc[mt][nt][2] + vb0, 0.f);
            float v11 = fmaxf(acc[mt][nt][3] + vb1, 0.f);
            #pragma unroll
            for (int o = 0; o < 4; o++) {
                o0[o] += v00 * w30[o] + v01 * w31[o];
                o1[o] += v10 * w30[o] + v11 * w31[o];
            }
        }
        #pragma unroll
        for (int off = 1; off <= 2; off <<= 1) {
            #pragma unroll
            for (int o = 0; o < 4; o++) {
                o0[o] += __shfl_xor_sync(0xffffffffu, o0[o], off);
                o1[o] += __shfl_xor_sync(0xffffffffu, o1[o], off);
            }
        }
        if (lc == 0) {
            int r0 = m0 + 16 * mt + lr;
            #pragma unroll
            for (int o = 0; o < 4; o++) {
                part[r0 * 16 + wl * 4 + o] = o0[o];
                part[(r0 + 8) * 16 + wl * 4 + o] = o1[o];
            }
        }
    }
    __syncthreads();

    if (t < 128) {
        float4 r;
        float s[4];
        #pragma unroll
        for (int o = 0; o < 4; o++) {
            s[o] = b3[o];
            #pragma unroll
            for (int w = 0; w < 4; w++) s[o] += part[t * 16 + w * 4 + o];
        }
        r.x = s[0]; r.y = s[1]; r.z = s[2]; r.w = s[3];
        *reinterpret_cast<float4*>(&out[((size_t)bn * NPAIR + t) * 4]) = r;
    }
}

extern "C" void kernel_launch(void* const* d_in, const int* in_sizes, int n_in,
                              void* d_out, int out_size)
{
    const float* f   = (const float*)d_in[0];
    const float* pos = (const float*)d_in[1];
    const float* W1  = (const float*)d_in[2];
    const float* b1  = (const float*)d_in[3];
    const float* W2  = (const float*)d_in[4];
    const float* b2  = (const float*)d_in[5];
    const float* W3  = (const float*)d_in[6];
    const float* b3  = (const float*)d_in[7];
    float* out = (float*)d_out;

    cudaFuncSetAttribute(k2_mma, cudaFuncAttributeMaxDynamicSharedMemorySize, SMEM_TOTAL);

    k1_precompute<<<dim3(8, 96), 256>>>(f, pos, W1, b1, W2);
    k2_mma<<<1024, 512, SMEM_TOTAL>>>(b2, W3, b3, out);
}